// round 4
// baseline (speedup 1.0000x reference)
#include <cuda_runtime.h>

// ---------------------------------------------------------------------------
// YOLOv3 detection post-process, round 4: single persistent kernel,
// 148 blocks x 1024 threads, 4 grid barriers.
//   S1 conf+hist | barA | S2 cutoff(all)+gather | barB |
//   S3 sort(blk0) PARALLEL decode-unsorted(blk1..147) | barC |
//   S4 iou bitmask + state resets | barD | S5 serial NMS + output (blk0)
// ---------------------------------------------------------------------------

#define NTOT   340704
#define N13    16224      // 32*3*13*13
#define OFF26  16224
#define OFF52  81120      // N13 + N26
#define CAP    4096
#define NBINS  4096
#define TOPK   512
#define GRID   148
#define BLK    1024
#define NTHR   (GRID * BLK)

__device__ unsigned            g_barcnt;      // self-resetting
__device__ unsigned            g_barsense;    // monotone across replays
__device__ unsigned            g_hist[NBINS]; // reset in S4
__device__ unsigned            g_count;       // reset in S4
__device__ unsigned long long  g_keys[CAP];
__device__ unsigned            g_perm[TOPK];  // sorted rank -> gather pos
__device__ int                 g_Mv;
__device__ float               g_cand[CAP * 7];   // indexed by gather pos
__device__ unsigned            g_mask[TOPK * 16];

__constant__ float c_anchors[3][3][2] = {
    {{116.f, 90.f}, {156.f, 198.f}, {373.f, 326.f}},   // 13x13, stride 32
    {{ 30.f, 61.f}, { 62.f,  45.f}, { 59.f, 119.f}},   // 26x26, stride 16
    {{ 10.f, 13.f}, { 16.f,  30.f}, { 33.f,  23.f}}};  // 52x52, stride 8
__constant__ float c_stride[3] = {32.f, 16.f, 8.f};

struct Sh {
    union {
        struct { unsigned long long sk[CAP]; unsigned sv[CAP]; } sort; // 48 KB
        unsigned mask[TOPK * 16];                                      // 32 KB
    } u;
    unsigned sense;
    unsigned psum[256];
    int      s_seg;
    unsigned s_cumafter;
    int      s_cut;
    unsigned keep[16];
};

__device__ __forceinline__ void grid_bar(Sh* sh) {
    __syncthreads();
    if (threadIdx.x == 0) {
        unsigned target = ++sh->sense;
        __threadfence();
        if (atomicAdd(&g_barcnt, 1u) == GRID - 1) {
            g_barcnt = 0;
            __threadfence();
            atomicExch(&g_barsense, target);
        } else {
            while (atomicAdd(&g_barsense, 0u) != target) __nanosleep(32);
        }
        __threadfence();
    }
    __syncthreads();
}

__device__ __forceinline__ float sigm(float x) { return 1.0f / (1.0f + expf(-x)); }

// Compile-time HW -> divisions become multiplies.
template<int HW, int OFFT>
__device__ __forceinline__ void decomp(int t, int& b, int& a, int& p) {
    int t2 = t - OFFT;
    b = t2 / (3 * HW);
    int r = t2 - b * 3 * HW;
    a = r / HW;
    p = r - a * HW;
}

template<int HW>
__device__ __forceinline__ float logit_at(const float* __restrict__ in,
                                          int b, int a, int p) {
    return in[(b * 255 + a * 85 + 4) * HW + p];
}

// warp-collective decode of one candidate (ref index g within scale sc)
template<int HW, int W, int SC>
__device__ __forceinline__ void decode_one(const float* __restrict__ in,
                                           unsigned g, float conf, int lane,
                                           float* __restrict__ o) {
    int a  = g % 3;
    int p  = g / 3;
    int b  = p / HW;
    int pp = p - b * HW;
    int x  = pp % W;
    int y  = pp / W;
    const float* base = in + (b * 255 + a * 85) * HW + pp;
    float chv = (lane < 4) ? base[lane * HW] : 0.f;
    float bv = -3.4e38f; int bi = 127;
#pragma unroll
    for (int k = 0; k < 3; k++) {
        int c = lane + 32 * k;
        if (c < 80) {
            float v = base[(5 + c) * HW];
            if (v > bv) { bv = v; bi = c; }
        }
    }
#pragma unroll
    for (int off = 16; off; off >>= 1) {
        float ov = __shfl_xor_sync(0xFFFFFFFFu, bv, off);
        int   oi = __shfl_xor_sync(0xFFFFFFFFu, bi, off);
        if (ov > bv || (ov == bv && oi < bi)) { bv = ov; bi = oi; }
    }
    float t0 = __shfl_sync(0xFFFFFFFFu, chv, 0);
    float t1 = __shfl_sync(0xFFFFFFFFu, chv, 1);
    float t2 = __shfl_sync(0xFFFFFFFFu, chv, 2);
    float t3 = __shfl_sync(0xFFFFFFFFu, chv, 3);
    if (lane == 0) {
        float st = c_stride[SC];
        float cx = ((float)x + sigm(t0)) * st;
        float cy = ((float)y + sigm(t1)) * st;
        float w  = c_anchors[SC][a][0] * expf(t2);
        float h  = c_anchors[SC][a][1] * expf(t3);
        float w0 = w * 0.5f, h0 = h * 0.5f;
        o[0] = conf;
        o[1] = cx - w0;
        o[2] = cy - h0;
        o[3] = cx + w0;
        o[4] = cy + h0;
        o[5] = (float)bi;
        o[6] = (float)b;
    }
}

// ---------------------------------------------------------------------------
__global__ void __launch_bounds__(BLK, 1)
detector_fused(const float* __restrict__ in13,
               const float* __restrict__ in26,
               const float* __restrict__ in52,
               float* __restrict__ out) {
    __shared__ Sh sh;
    int tid = threadIdx.x;
    int gid = blockIdx.x * BLK + tid;

    if (tid == 0) sh.sense = atomicAdd(&g_barsense, 0u);
    __syncthreads();

    // ---- S1: conf + histogram --------------------------------------------
#pragma unroll
    for (int k = 0; k < 3; k++) {
        int t = gid + k * NTHR;
        if (t >= NTOT) break;
        float logit;
        if (t < N13) {
            int b, a, p; decomp<169, 0>(t, b, a, p);
            logit = logit_at<169>(in13, b, a, p);
        } else if (t < OFF52) {
            int b, a, p; decomp<676, OFF26>(t, b, a, p);
            logit = logit_at<676>(in26, b, a, p);
        } else {
            int b, a, p; decomp<2704, OFF52>(t, b, a, p);
            logit = logit_at<2704>(in52, b, a, p);
        }
        float conf = sigm(logit);
        if (conf > 0.5f) {
            unsigned bin = (__float_as_uint(conf) - 0x3F000000u) >> 11;
            if (bin > NBINS - 1) bin = NBINS - 1;
            atomicAdd(&g_hist[bin], 1u);
        }
    }
    grid_bar(&sh);

    // ---- S2a: cutoff (every block, redundant) ------------------------------
    {
        unsigned loc[16];
        if (tid < 256) {
            unsigned s = 0;
#pragma unroll
            for (int k = 0; k < 16; k++) { loc[k] = g_hist[tid * 16 + k]; s += loc[k]; }
            sh.psum[tid] = s;
        }
        __syncthreads();
        if (tid == 0) {
            unsigned cum = 0; int seg = -1;
            for (int i = 255; i >= 0; --i) {
                if (cum + sh.psum[i] >= TOPK) { seg = i; break; }
                cum += sh.psum[i];
            }
            sh.s_seg = seg; sh.s_cumafter = cum;
            if (seg < 0) sh.s_cut = 0;
        }
        __syncthreads();
        if (tid < 256 && tid == sh.s_seg) {
            unsigned cum = sh.s_cumafter;
            int cb = tid * 16;
            for (int k = 15; k >= 0; --k) {
                cum += loc[k];
                if (cum >= TOPK) { cb = tid * 16 + k; break; }
            }
            sh.s_cut = cb;
        }
        __syncthreads();
    }
    int cut = sh.s_cut;

    // ---- S2b: gather --------------------------------------------------------
#pragma unroll
    for (int k = 0; k < 3; k++) {
        int t = gid + k * NTHR;
        if (t >= NTOT) break;
        float logit; unsigned g;
        if (t < N13) {
            int b, a, p; decomp<169, 0>(t, b, a, p);
            logit = logit_at<169>(in13, b, a, p);
            g = (unsigned)((b * 169 + p) * 3 + a);
        } else if (t < OFF52) {
            int b, a, p; decomp<676, OFF26>(t, b, a, p);
            logit = logit_at<676>(in26, b, a, p);
            g = (unsigned)(OFF26 + (b * 676 + p) * 3 + a);
        } else {
            int b, a, p; decomp<2704, OFF52>(t, b, a, p);
            logit = logit_at<2704>(in52, b, a, p);
            g = (unsigned)(OFF52 + (b * 2704 + p) * 3 + a);
        }
        float conf = sigm(logit);
        if (!(conf > 0.5f)) continue;
        unsigned bits = __float_as_uint(conf);
        unsigned bin  = (bits - 0x3F000000u) >> 11;
        if (bin > NBINS - 1) bin = NBINS - 1;
        if ((int)bin < cut) continue;
        unsigned pos = atomicAdd(&g_count, 1u);
        if (pos < CAP)
            g_keys[pos] = ((unsigned long long)bits << 32) | (0xFFFFFFFFu - g);
    }
    grid_bar(&sh);

    // ---- S3: block0 sorts keys+payload; blocks 1..147 decode unsorted -------
    int Mcnt = (int)atomicAdd(&g_count, 0u);   // stable after barB
    if (Mcnt > CAP) Mcnt = CAP;
    if (blockIdx.x == 0) {
        int n = TOPK; while (n < Mcnt) n <<= 1;
        if (tid == 0) g_Mv = (Mcnt < TOPK) ? Mcnt : TOPK;
        for (int k = tid; k < n; k += BLK) {
            sh.u.sort.sk[k] = (k < Mcnt) ? g_keys[k] : 0ull;
            sh.u.sort.sv[k] = (unsigned)k;
        }
        for (int ksz = 2; ksz <= n; ksz <<= 1)
            for (int j = ksz >> 1; j > 0; j >>= 1) {
                __syncthreads();
                for (int i = tid; i < n; i += BLK) {
                    int l = i ^ j;
                    if (l > i) {
                        unsigned long long A = sh.u.sort.sk[i], B = sh.u.sort.sk[l];
                        bool dec = ((i & ksz) == 0);
                        if (dec ? (A < B) : (A > B)) {
                            sh.u.sort.sk[i] = B; sh.u.sort.sk[l] = A;
                            unsigned va = sh.u.sort.sv[i];
                            sh.u.sort.sv[i] = sh.u.sort.sv[l];
                            sh.u.sort.sv[l] = va;
                        }
                    }
                }
            }
        __syncthreads();
        for (int r = tid; r < TOPK; r += BLK) g_perm[r] = sh.u.sort.sv[r];
    } else {
        int w = (blockIdx.x - 1) * (BLK >> 5) + (tid >> 5);
        int lane = tid & 31;
        if (w < Mcnt) {
            unsigned long long key = g_keys[w];
            float conf = __uint_as_float((unsigned)(key >> 32));
            unsigned g = 0xFFFFFFFFu - (unsigned)(key & 0xFFFFFFFFu);
            float* o = &g_cand[w * 7];
            if (g < N13)        decode_one<169, 13, 0>(in13, g, conf, lane, o);
            else if (g < OFF52) decode_one<676, 26, 1>(in26, g - OFF26, conf, lane, o);
            else                decode_one<2704, 52, 2>(in52, g - OFF52, conf, lane, o);
        }
    }
    grid_bar(&sh);

    // ---- S4: IoU bit-matrix (sorted-rank space via perm) + resets -----------
    {
        int Mv = g_Mv;
        int j = tid & 511, half = tid >> 9;
        float jx1 = 0.f, jy1 = 0.f, jx2 = 0.f, jy2 = 0.f, areaJ = 0.f;
        bool jv = (j < Mv);
        if (jv) {
            const float* c = &g_cand[g_perm[j] * 7];
            jx1 = c[1]; jy1 = c[2]; jx2 = c[3]; jy2 = c[4];
            areaJ = fmaxf(jx2 - jx1, 0.f) * fmaxf(jy2 - jy1, 0.f);
        }
        for (int i = blockIdx.x * 2 + half; i < TOPK; i += 2 * GRID) {
            unsigned bal = 0u;
            if (i < Mv) {
                const float* c = &g_cand[g_perm[i] * 7];
                float ix1 = c[1], iy1 = c[2], ix2 = c[3], iy2 = c[4];
                float areaI = fmaxf(ix2 - ix1, 0.f) * fmaxf(iy2 - iy1, 0.f);
                float xx1 = fmaxf(ix1, jx1), yy1 = fmaxf(iy1, jy1);
                float xx2 = fminf(ix2, jx2), yy2 = fminf(iy2, jy2);
                float inter = fmaxf(xx2 - xx1, 0.f) * fmaxf(yy2 - yy1, 0.f);
                float iou = inter / (areaI + areaJ - inter + 1e-9f);
                bal = __ballot_sync(0xFFFFFFFFu, jv && (j > i) && (iou > 0.3f));
            }
            if ((tid & 31) == 0) g_mask[i * 16 + (j >> 5)] = bal;
        }
        // state resets for next replay (safe: all readers passed barC)
        if (gid < NBINS) g_hist[gid] = 0u;
        if (blockIdx.x == 1 && tid == 0) g_count = 0u;
    }
    grid_bar(&sh);

    // ---- S5: serial greedy NMS + output (block 0 only) ----------------------
    if (blockIdx.x != 0) return;
    {
        int Mv = g_Mv;
        for (int idx = tid; idx < TOPK * 16; idx += BLK)
            sh.u.mask[idx] = g_mask[idx];
        if (tid < 16) {
            int lo = tid * 32;
            unsigned w;
            if (Mv >= lo + 32)      w = 0xFFFFFFFFu;
            else if (Mv <= lo)      w = 0u;
            else                    w = (1u << (Mv - lo)) - 1u;
            sh.keep[tid] = w;
        }
        __syncthreads();
        if (tid == 0) {
            unsigned kw[16];
#pragma unroll
            for (int k = 0; k < 16; k++) kw[k] = sh.keep[k];
            for (int w = 0; w < 16; w++) {
                unsigned bits = kw[w];
                while (bits) {
                    int b = __ffs(bits) - 1;
                    const unsigned* mrow = &sh.u.mask[(w * 32 + b) * 16];
                    for (int u = w; u < 16; u++) kw[u] &= ~mrow[u];
                    bits = kw[w] & (0xFFFFFFFEu << b);
                }
            }
#pragma unroll
            for (int k = 0; k < 16; k++) sh.keep[k] = kw[k];
        }
        __syncthreads();
        for (int idx = tid; idx < TOPK * 7; idx += BLK) {
            int r = idx / 7;
            int c = idx - r * 7;
            float v = 0.f;
            if ((sh.keep[r >> 5] >> (r & 31)) & 1u)
                v = g_cand[g_perm[r] * 7 + c];
            out[idx] = v;
        }
    }
}

// ---------------------------------------------------------------------------
extern "C" void kernel_launch(void* const* d_in, const int* in_sizes, int n_in,
                              void* d_out, int out_size) {
    const float* in13 = (const float*)d_in[0];
    const float* in26 = (const float*)d_in[1];
    const float* in52 = (const float*)d_in[2];
    float* out = (float*)d_out;
    detector_fused<<<GRID, BLK>>>(in13, in26, in52, out);
}

// round 5
// speedup vs baseline: 3.1972x; 3.1972x over previous
#include <cuda_runtime.h>

// ---------------------------------------------------------------------------
// YOLOv3 detection post-process, round 5: multi-kernel, zero serial stages.
//  k_conf (hist) -> k_cutoff (parallel scan) -> k_gather -> k_decode(gather
//  order) -> k_rank (sort-free permutation) -> k_iou (+state resets) ->
//  k_nms_out (warp-cooperative greedy).
// ---------------------------------------------------------------------------

#define NTOT   340704
#define N13    16224      // 32*3*13*13
#define OFF26  16224
#define OFF52  81120      // N13 + N26
#define CAP    4096
#define NBINS  4096
#define TOPK   512

__device__ unsigned            g_hist[NBINS];   // zero-init; reset by k_iou
__device__ int                 g_cutoff;
__device__ unsigned            g_count;         // zero-init; reset by k_iou
__device__ unsigned long long  g_keys[CAP];
__device__ unsigned            g_perm[TOPK];    // rank -> gather pos
__device__ int                 g_Mv;
__device__ float               g_cand[CAP * 7]; // by gather pos
__device__ unsigned            g_mask[TOPK * 16];

__constant__ float c_anchors[3][3][2] = {
    {{116.f, 90.f}, {156.f, 198.f}, {373.f, 326.f}},   // 13x13, stride 32
    {{ 30.f, 61.f}, { 62.f,  45.f}, { 59.f, 119.f}},   // 26x26, stride 16
    {{ 10.f, 13.f}, { 16.f,  30.f}, { 33.f,  23.f}}};  // 52x52, stride 8
__constant__ float c_stride[3] = {32.f, 16.f, 8.f};

__device__ __forceinline__ float sigm(float x) { return 1.0f / (1.0f + expf(-x)); }

// Compile-time HW -> all divisions become mul/shift.
template<int HW, int OFFT>
__device__ __forceinline__ void decomp(int t, int& b, int& a, int& p) {
    int t2 = t - OFFT;
    b = t2 / (3 * HW);
    int r = t2 - b * 3 * HW;
    a = r / HW;
    p = r - a * HW;
}

// ---------------------------------------------------------------------------
__global__ void __launch_bounds__(256) k_conf(const float* __restrict__ in13,
                                              const float* __restrict__ in26,
                                              const float* __restrict__ in52) {
    int base = blockIdx.x * 1024 + threadIdx.x;
#pragma unroll
    for (int k = 0; k < 4; k++) {
        int t = base + k * 256;
        if (t >= NTOT) break;
        float logit;
        if (t < N13) {
            int b, a, p; decomp<169, 0>(t, b, a, p);
            logit = in13[(b * 255 + a * 85 + 4) * 169 + p];
        } else if (t < OFF52) {
            int b, a, p; decomp<676, OFF26>(t, b, a, p);
            logit = in26[(b * 255 + a * 85 + 4) * 676 + p];
        } else {
            int b, a, p; decomp<2704, OFF52>(t, b, a, p);
            logit = in52[(b * 255 + a * 85 + 4) * 2704 + p];
        }
        float conf = sigm(logit);
        if (conf > 0.5f) {
            unsigned bin = (__float_as_uint(conf) - 0x3F000000u) >> 11;
            if (bin > NBINS - 1) bin = NBINS - 1;
            atomicAdd(&g_hist[bin], 1u);
        }
    }
}

// ---------------------------------------------------------------------------
__global__ void __launch_bounds__(256) k_cutoff() {
    __shared__ unsigned S[256];
    int t = threadIdx.x;
    unsigned loc[16];
    unsigned s = 0;
#pragma unroll
    for (int k = 0; k < 16; k++) { loc[k] = g_hist[t * 16 + k]; s += loc[k]; }
    S[t] = s;
    // Hillis-Steele suffix sum
    for (int d = 1; d < 256; d <<= 1) {
        __syncthreads();
        unsigned add = (t + d < 256) ? S[t + d] : 0u;
        __syncthreads();
        S[t] += add;
    }
    __syncthreads();
    unsigned Sn = (t + 1 < 256) ? S[t + 1] : 0u;
    if (t == 0 && S[0] < TOPK) g_cutoff = 0;   // fewer than TOPK valid
    if (S[t] >= TOPK && Sn < TOPK) {           // exactly one t (monotone)
        unsigned cum = Sn;
        int cb = t * 16;
        for (int k = 15; k >= 0; --k) {
            cum += loc[k];
            if (cum >= TOPK) { cb = t * 16 + k; break; }
        }
        g_cutoff = cb;
    }
}

// ---------------------------------------------------------------------------
__global__ void __launch_bounds__(256) k_gather(const float* __restrict__ in13,
                                                const float* __restrict__ in26,
                                                const float* __restrict__ in52) {
    int base = blockIdx.x * 1024 + threadIdx.x;
    int cut = g_cutoff;
#pragma unroll
    for (int k = 0; k < 4; k++) {
        int t = base + k * 256;
        if (t >= NTOT) break;
        float logit; unsigned g;
        if (t < N13) {
            int b, a, p; decomp<169, 0>(t, b, a, p);
            logit = in13[(b * 255 + a * 85 + 4) * 169 + p];
            g = (unsigned)((b * 169 + p) * 3 + a);
        } else if (t < OFF52) {
            int b, a, p; decomp<676, OFF26>(t, b, a, p);
            logit = in26[(b * 255 + a * 85 + 4) * 676 + p];
            g = (unsigned)(OFF26 + (b * 676 + p) * 3 + a);
        } else {
            int b, a, p; decomp<2704, OFF52>(t, b, a, p);
            logit = in52[(b * 255 + a * 85 + 4) * 2704 + p];
            g = (unsigned)(OFF52 + (b * 2704 + p) * 3 + a);
        }
        float conf = sigm(logit);
        if (!(conf > 0.5f)) continue;
        unsigned bits = __float_as_uint(conf);
        unsigned bin  = (bits - 0x3F000000u) >> 11;
        if (bin > NBINS - 1) bin = NBINS - 1;
        if ((int)bin < cut) continue;
        unsigned pos = atomicAdd(&g_count, 1u);
        if (pos < CAP)
            g_keys[pos] = ((unsigned long long)bits << 32) | (0xFFFFFFFFu - g);
    }
}

// ---------------------------------------------------------------------------
// Warp-collective decode of one candidate in gather order.
template<int HW, int W, int SC>
__device__ __forceinline__ void decode_one(const float* __restrict__ in,
                                           unsigned g, float conf, int lane,
                                           float* __restrict__ o) {
    int a  = g % 3;
    int p  = g / 3;
    int b  = p / HW;
    int pp = p - b * HW;
    int x  = pp % W;
    int y  = pp / W;
    const float* base = in + (b * 255 + a * 85) * HW + pp;
    float chv = (lane < 4) ? base[lane * HW] : 0.f;
    float bv = -3.4e38f; int bi = 127;
#pragma unroll
    for (int k = 0; k < 3; k++) {
        int c = lane + 32 * k;
        if (c < 80) {
            float v = base[(5 + c) * HW];
            if (v > bv) { bv = v; bi = c; }
        }
    }
#pragma unroll
    for (int off = 16; off; off >>= 1) {
        float ov = __shfl_xor_sync(0xFFFFFFFFu, bv, off);
        int   oi = __shfl_xor_sync(0xFFFFFFFFu, bi, off);
        if (ov > bv || (ov == bv && oi < bi)) { bv = ov; bi = oi; }
    }
    float t0 = __shfl_sync(0xFFFFFFFFu, chv, 0);
    float t1 = __shfl_sync(0xFFFFFFFFu, chv, 1);
    float t2 = __shfl_sync(0xFFFFFFFFu, chv, 2);
    float t3 = __shfl_sync(0xFFFFFFFFu, chv, 3);
    if (lane == 0) {
        float st = c_stride[SC];
        float cx = ((float)x + sigm(t0)) * st;
        float cy = ((float)y + sigm(t1)) * st;
        float w  = c_anchors[SC][a][0] * expf(t2);
        float h  = c_anchors[SC][a][1] * expf(t3);
        float w0 = w * 0.5f, h0 = h * 0.5f;
        o[0] = conf;
        o[1] = cx - w0;
        o[2] = cy - h0;
        o[3] = cx + w0;
        o[4] = cy + h0;
        o[5] = (float)bi;
        o[6] = (float)b;
    }
}

__global__ void __launch_bounds__(256) k_decode(const float* __restrict__ in13,
                                                const float* __restrict__ in26,
                                                const float* __restrict__ in52) {
    if (blockIdx.x == 0 && threadIdx.x == 0) {
        int M = (int)g_count; if (M > CAP) M = CAP;
        g_Mv = (M < TOPK) ? M : TOPK;
    }
    int M = (int)g_count; if (M > CAP) M = CAP;
    int nwarps = gridDim.x * (blockDim.x >> 5);
    int w0   = blockIdx.x * (blockDim.x >> 5) + (threadIdx.x >> 5);
    int lane = threadIdx.x & 31;
    for (int w = w0; w < M; w += nwarps) {
        unsigned long long key = g_keys[w];
        float conf = __uint_as_float((unsigned)(key >> 32));
        unsigned g = 0xFFFFFFFFu - (unsigned)(key & 0xFFFFFFFFu);
        float* o = &g_cand[w * 7];
        if (g < N13)        decode_one<169, 13, 0>(in13, g, conf, lane, o);
        else if (g < OFF52) decode_one<676, 26, 1>(in26, g - OFF26, conf, lane, o);
        else                decode_one<2704, 52, 2>(in52, g - OFF52, conf, lane, o);
    }
}

// ---------------------------------------------------------------------------
// Sort-free ranking: rank(i) = #{j : key_j > key_i}; keys unique.
__global__ void __launch_bounds__(256) k_rank() {
    int M = (int)g_count; if (M > CAP) M = CAP;
    int nwarps = gridDim.x * (blockDim.x >> 5);
    int w0   = blockIdx.x * (blockDim.x >> 5) + (threadIdx.x >> 5);
    int lane = threadIdx.x & 31;
    for (int i = w0; i < M; i += nwarps) {
        unsigned long long ki = g_keys[i];
        int rank = 0;
        for (int j0 = 0; j0 < M; j0 += 32) {
            int j = j0 + lane;
            unsigned long long kj = (j < M) ? g_keys[j] : 0ull;
            rank += __popc(__ballot_sync(0xFFFFFFFFu, (j < M) && (kj > ki)));
        }
        if (lane == 0 && rank < TOPK) g_perm[rank] = (unsigned)i;
    }
}

// ---------------------------------------------------------------------------
// 64 blocks x 512: bit (i,j) in rank space; also resets hist/count for replay.
__global__ void __launch_bounds__(512) k_iou() {
    int Mv = g_Mv;
    int j = threadIdx.x;
    bool jv = (j < Mv);
    float jx1 = 0.f, jy1 = 0.f, jx2 = 0.f, jy2 = 0.f, areaJ = 0.f;
    if (jv) {
        const float* c = &g_cand[(g_perm[j] & (CAP - 1)) * 7];
        jx1 = c[1]; jy1 = c[2]; jx2 = c[3]; jy2 = c[4];
        areaJ = fmaxf(jx2 - jx1, 0.f) * fmaxf(jy2 - jy1, 0.f);
    }
    int wid = j >> 5, lane = j & 31;
#pragma unroll
    for (int q = 0; q < 8; q++) {
        int i = blockIdx.x * 8 + q;
        float ix1 = 0.f, iy1 = 0.f, ix2 = 0.f, iy2 = 0.f, areaI = 0.f;
        if (i < Mv) {
            const float* c = &g_cand[(g_perm[i] & (CAP - 1)) * 7];
            ix1 = c[1]; iy1 = c[2]; ix2 = c[3]; iy2 = c[4];
            areaI = fmaxf(ix2 - ix1, 0.f) * fmaxf(iy2 - iy1, 0.f);
        }
        float xx1 = fmaxf(ix1, jx1), yy1 = fmaxf(iy1, jy1);
        float xx2 = fminf(ix2, jx2), yy2 = fminf(iy2, jy2);
        float inter = fmaxf(xx2 - xx1, 0.f) * fmaxf(yy2 - yy1, 0.f);
        float iou = inter / (areaI + areaJ - inter + 1e-9f);
        unsigned bal = __ballot_sync(0xFFFFFFFFu,
                                     jv && (i < Mv) && (j > i) && (iou > 0.3f));
        if (lane == 0) g_mask[i * 16 + wid] = bal;
    }
    // state resets for the next replay (g_count/g_hist no longer read)
    int gid = blockIdx.x * 512 + threadIdx.x;
    if (gid < NBINS) g_hist[gid] = 0u;
    if (gid == 0) g_count = 0u;
}

// ---------------------------------------------------------------------------
__global__ void __launch_bounds__(512) k_nms_out(float* __restrict__ out) {
    __shared__ unsigned smask[TOPK * 16];   // 32 KB
    __shared__ unsigned skeep[16];
    int tid = threadIdx.x;
    int Mv = g_Mv;
    for (int idx = tid; idx < TOPK * 16; idx += 512)
        smask[idx] = g_mask[idx];
    __syncthreads();

    if (tid < 32) {
        int lane = tid;
        unsigned kw = 0u;
        if (lane < 16) {
            int lo = lane * 32;
            if (Mv >= lo + 32)      kw = 0xFFFFFFFFu;
            else if (Mv > lo)       kw = (1u << (Mv - lo)) - 1u;
        }
        unsigned kept = 0u;
        while (true) {
            unsigned ball = __ballot_sync(0xFFFFFFFFu, kw != 0u);
            if (!ball) break;
            int wsel = __ffs(ball) - 1;
            unsigned word = __shfl_sync(0xFFFFFFFFu, kw, wsel);
            int b = __ffs(word) - 1;
            int p = wsel * 32 + b;
            if (lane == wsel) { kept |= (1u << b); kw &= ~(1u << b); }
            unsigned row = (lane < 16) ? smask[p * 16 + lane] : 0u;
            kw &= ~row;
        }
        if (lane < 16) skeep[lane] = kept;
    }
    __syncthreads();

    for (int idx = tid; idx < TOPK * 7; idx += 512) {
        int r = idx / 7;
        int c = idx - r * 7;
        float v = 0.f;
        if ((skeep[r >> 5] >> (r & 31)) & 1u)
            v = g_cand[(g_perm[r] & (CAP - 1)) * 7 + c];
        out[idx] = v;
    }
}

// ---------------------------------------------------------------------------
extern "C" void kernel_launch(void* const* d_in, const int* in_sizes, int n_in,
                              void* d_out, int out_size) {
    const float* in13 = (const float*)d_in[0];
    const float* in26 = (const float*)d_in[1];
    const float* in52 = (const float*)d_in[2];
    float* out = (float*)d_out;

    int pass_blocks = (NTOT + 1023) / 1024;          // 333
    k_conf  <<<pass_blocks, 256>>>(in13, in26, in52);
    k_cutoff<<<1, 256>>>();
    k_gather<<<pass_blocks, 256>>>(in13, in26, in52);
    k_decode<<<128, 256>>>(in13, in26, in52);
    k_rank  <<<128, 256>>>();
    k_iou   <<<64, 512>>>();
    k_nms_out<<<1, 512>>>(out);
}